// round 1
// baseline (speedup 1.0000x reference)
#include <cuda_runtime.h>
#include <cuda_fp16.h>
#include <cstdint>

#define NB   16
#define CIN  512
#define COUT 512
#define HH   64
#define WWD  64
#define KKC  256   // channel pairs (half2)

// ---------------- device scratch (static, allowed) ----------------
static __device__ float   g_style[NB * CIN];
static __device__ float   g_wsq[COUT * CIN];
static __device__ float   g_demod[NB * COUT];
static __device__ __half2 g_x2[(size_t)NB * KKC * HH * WWD];   // [b][kk][y][x], 67MB
static __device__ __half2 g_wh2[KKC * 9 * COUT];               // [kk][tap][o], 4.7MB

// ---------------- prep kernels ----------------
__global__ void style_kernel(const float* __restrict__ w,
                             const float* __restrict__ mw,
                             const float* __restrict__ mb) {
    __shared__ float sw[512];
    int b = blockIdx.x, c = threadIdx.x;
    sw[c] = w[b * 512 + c];
    __syncthreads();
    float acc = 0.f;
    const float* row = mw + c * 512;
#pragma unroll 8
    for (int d = 0; d < 512; d++) acc += sw[d] * row[d];
    // MOD_WEIGHT_GAIN = 1/sqrt(512)
    g_style[b * 512 + c] = acc * 0.04419417382415922f + mb[c];
}

__global__ void wsq_kernel(const float* __restrict__ weight) {
    int o = blockIdx.x, c = threadIdx.x;
    const float* p = weight + (o * 512 + c) * 9;
    float s = 0.f;
#pragma unroll
    for (int t = 0; t < 9; t++) { float v = p[t]; s += v * v; }
    g_wsq[o * 512 + c] = s;
}

__global__ void demod_kernel() {
    int gid = blockIdx.x * blockDim.x + threadIdx.x;  // 8192 threads
    int o = gid >> 4, b = gid & 15;
    const float* wq = g_wsq + o * 512;
    const float* st = g_style + b * 512;
    float s = 0.f;
#pragma unroll 8
    for (int c = 0; c < 512; c++) { float t = st[c]; s += wq[c] * t * t; }
    const float WG2 = 1.0f / (512.f * 9.f);   // WEIGHT_GAIN^2
    g_demod[b * 512 + o] = rsqrtf(s * WG2 + 1e-8f);
}

__global__ void xscale_kernel(const float* __restrict__ x) {
    int idx = blockIdx.x * blockDim.x + threadIdx.x;  // 4.19M threads
    int x4 = idx & 15;
    int y  = (idx >> 4) & 63;
    int kk = (idx >> 10) & 255;
    int b  = idx >> 18;
    float se = g_style[b * 512 + 2 * kk];
    float so = g_style[b * 512 + 2 * kk + 1];
    const float4* xp = reinterpret_cast<const float4*>(x);
    float4 xe = xp[(b * 512 + 2 * kk) * 1024 + y * 16 + x4];
    float4 xo = xp[(b * 512 + 2 * kk + 1) * 1024 + y * 16 + x4];
    __half2 h[4];
    h[0] = __floats2half2_rn(xe.x * se, xo.x * so);
    h[1] = __floats2half2_rn(xe.y * se, xo.y * so);
    h[2] = __floats2half2_rn(xe.z * se, xo.z * so);
    h[3] = __floats2half2_rn(xe.w * se, xo.w * so);
    reinterpret_cast<uint4*>(g_x2)[(b * 256 + kk) * 1024 + y * 16 + x4] =
        *reinterpret_cast<uint4*>(h);
}

__global__ void wh2_kernel(const float* __restrict__ weight) {
    int o  = threadIdx.x;            // 512
    int kk = blockIdx.x / 9;
    int t  = blockIdx.x % 9;
    const float WG = 0.014731391274719739f;  // 1/sqrt(512*9)
    float we = weight[(o * 512 + 2 * kk) * 9 + t] * WG;
    float wo = weight[(o * 512 + 2 * kk + 1) * 9 + t] * WG;
    g_wh2[(kk * 9 + t) * 512 + o] = __floats2half2_rn(we, wo);
}

// ---------------- conv: implicit GEMM, fp16 mma.sync, fp32 accum ----------------
__device__ __forceinline__ void mma16816(float& c0, float& c1, float& c2, float& c3,
                                         uint32_t a0, uint32_t a1, uint32_t a2, uint32_t a3,
                                         uint32_t b0, uint32_t b1) {
    asm volatile(
        "mma.sync.aligned.m16n8k16.row.col.f32.f16.f16.f32 "
        "{%0,%1,%2,%3}, {%4,%5,%6,%7}, {%8,%9}, {%0,%1,%2,%3};\n"
        : "+f"(c0), "+f"(c1), "+f"(c2), "+f"(c3)
        : "r"(a0), "r"(a1), "r"(a2), "r"(a3), "r"(b0), "r"(b1));
}

#define XS_K 440          // half2 stride per kk: 6*72 rows + 8 pad (bank-conflict-free)
#define XS_R 72           // half2 stride per input row (66 used)
#define WS_T (16 * 72)    // half2 stride per tap
#define WS_K 72           // half2 stride per kk (64 used)

__global__ void __launch_bounds__(256, 2) conv_kernel(float* __restrict__ out) {
    extern __shared__ __align__(16) __half2 smem[];
    __half2* Xs = smem;                 // [16 kk][6 rows][72 cols]
    __half2* Ws = smem + 16 * XS_K;     // [9 tap][16 kk][72 n]

    const int n0  = blockIdx.x * 64;
    const int y0  = blockIdx.y * 4;
    const int b   = blockIdx.z;
    const int tid = threadIdx.x;
    const int w = tid >> 5, lane = tid & 31;
    const int g = lane >> 2, t4 = lane & 3;
    const int r = w >> 1, xb = (w & 1) * 32;   // warp: image row r (of 4), x half

    float acc[64];
#pragma unroll
    for (int i = 0; i < 64; i++) acc[i] = 0.f;

    for (int kk0 = 0; kk0 < 256; kk0 += 16) {   // 32 input channels per chunk
        __syncthreads();
        // load X slab: rows y0-1 .. y0+4, cols -1..64 (zero padded)
        for (int idx = tid; idx < 16 * 6 * 66; idx += 256) {
            int kkL = idx / (6 * 66);
            int rem = idx - kkL * (6 * 66);
            int rr = rem / 66, j = rem - rr * 66;
            int yy = y0 - 1 + rr;
            __half2 v = __float2half2_rn(0.f);
            if (j >= 1 && j <= 64 && yy >= 0 && yy < 64)
                v = g_x2[((b * 256 + kk0 + kkL) * 64 + yy) * 64 + (j - 1)];
            Xs[kkL * XS_K + rr * XS_R + j] = v;
        }
        // load weights for this chunk: 9 taps x 16 kk x 64 out-ch
        for (int idx = tid; idx < 9 * 16 * 64; idx += 256) {
            int tp = idx / (16 * 64);
            int rem = idx - tp * (16 * 64);
            int kkL = rem >> 6, n = rem & 63;
            Ws[tp * WS_T + kkL * WS_K + n] =
                g_wh2[((kk0 + kkL) * 9 + tp) * 512 + n0 + n];
        }
        __syncthreads();

#pragma unroll 1
        for (int tap = 0; tap < 9; tap++) {
            const int ky = tap / 3, kx = tap - ky * 3;
#pragma unroll
            for (int ks = 0; ks < 2; ks++) {          // two k16 halves of the chunk
                const int kkA = 8 * ks + t4;
                uint32_t a[2][4];
#pragma unroll
                for (int s = 0; s < 2; s++) {         // two m16 subtiles of warp m32
                    int col = xb + 16 * s + kx + g;
                    const __half2* base = Xs + kkA * XS_K + (r + ky) * XS_R;
                    a[s][0] = *reinterpret_cast<const uint32_t*>(base + col);
                    a[s][1] = *reinterpret_cast<const uint32_t*>(base + col + 8);
                    a[s][2] = *reinterpret_cast<const uint32_t*>(base + 4 * XS_K + col);
                    a[s][3] = *reinterpret_cast<const uint32_t*>(base + 4 * XS_K + col + 8);
                }
#pragma unroll
                for (int nc = 0; nc < 8; nc++) {
                    const __half2* wb = Ws + tap * WS_T + kkA * WS_K + nc * 8 + g;
                    uint32_t b0 = *reinterpret_cast<const uint32_t*>(wb);
                    uint32_t b1 = *reinterpret_cast<const uint32_t*>(wb + 4 * WS_K);
#pragma unroll
                    for (int s = 0; s < 2; s++) {
                        float* c = acc + (s * 8 + nc) * 4;
                        mma16816(c[0], c[1], c[2], c[3],
                                 a[s][0], a[s][1], a[s][2], a[s][3], b0, b1);
                    }
                }
            }
        }
    }

    // epilogue: multiply by demod, store fp32
    const int y = y0 + r;
#pragma unroll
    for (int nc = 0; nc < 8; nc++) {
        int o = n0 + nc * 8 + 2 * t4;
        float d0 = g_demod[b * 512 + o];
        float d1 = g_demod[b * 512 + o + 1];
        size_t base0 = (((size_t)b * 512 + o) * 64 + y) * 64;
#pragma unroll
        for (int s = 0; s < 2; s++) {
            int xx = xb + 16 * s + g;
            float* c = acc + (s * 8 + nc) * 4;
            out[base0 + xx]            = c[0] * d0;
            out[base0 + 4096 + xx]     = c[1] * d1;
            out[base0 + xx + 8]        = c[2] * d0;
            out[base0 + 4096 + xx + 8] = c[3] * d1;
        }
    }
}

// ---------------- launch ----------------
extern "C" void kernel_launch(void* const* d_in, const int* in_sizes, int n_in,
                              void* d_out, int out_size) {
    const float* x      = (const float*)d_in[0];   // [16,512,64,64]
    const float* w      = (const float*)d_in[1];   // [16,512]
    const float* weight = (const float*)d_in[2];   // [512,512,3,3]
    const float* mw     = (const float*)d_in[3];   // [512,512]
    const float* mb     = (const float*)d_in[4];   // [512]
    float* out = (float*)d_out;

    style_kernel<<<16, 512>>>(w, mw, mb);
    wsq_kernel<<<512, 512>>>(weight);
    demod_kernel<<<32, 256>>>();
    xscale_kernel<<<16384, 256>>>(x);
    wh2_kernel<<<256 * 9, 512>>>(weight);

    size_t shmem = (size_t)(16 * XS_K + 9 * WS_T) * sizeof(__half2);  // 69632 B
    cudaFuncSetAttribute(conv_kernel, cudaFuncAttributeMaxDynamicSharedMemorySize,
                         (int)shmem);
    dim3 grid(8, 16, 16);   // (out-ch/64, H/4, B)
    conv_kernel<<<grid, 256, shmem>>>(out);
}

// round 2
// speedup vs baseline: 1.3350x; 1.3350x over previous
#include <cuda_runtime.h>
#include <cuda_fp16.h>
#include <cstdint>

#define NB   16
#define CIN  512
#define COUT 512
#define HH   64
#define WWD  64
#define KKC  256   // channel pairs (half2)

// ---------------- device scratch (static, allowed) ----------------
static __device__ float   g_style[NB * CIN];
static __device__ float   g_wsq[COUT * CIN];
static __device__ float   g_demod[NB * COUT];
static __device__ __half2 g_x2[(size_t)NB * KKC * HH * WWD];   // [b][kk][y][x], 67MB
static __device__ __half2 g_wh2[KKC * 9 * COUT];               // [kk][tap][o], 4.7MB

// ---------------- prep kernels ----------------
__global__ void style_kernel(const float* __restrict__ w,
                             const float* __restrict__ mw,
                             const float* __restrict__ mb) {
    __shared__ float sw[512];
    int b = blockIdx.x, c = threadIdx.x;
    sw[c] = w[b * 512 + c];
    __syncthreads();
    float acc = 0.f;
    const float* row = mw + c * 512;
#pragma unroll 8
    for (int d = 0; d < 512; d++) acc += sw[d] * row[d];
    g_style[b * 512 + c] = acc * 0.04419417382415922f + mb[c];
}

__global__ void wsq_kernel(const float* __restrict__ weight) {
    int o = blockIdx.x, c = threadIdx.x;
    const float* p = weight + (o * 512 + c) * 9;
    float s = 0.f;
#pragma unroll
    for (int t = 0; t < 9; t++) { float v = p[t]; s += v * v; }
    g_wsq[o * 512 + c] = s;
}

__global__ void demod_kernel() {
    int gid = blockIdx.x * blockDim.x + threadIdx.x;  // 8192 threads
    int o = gid >> 4, b = gid & 15;
    const float* wq = g_wsq + o * 512;
    const float* st = g_style + b * 512;
    float s = 0.f;
#pragma unroll 8
    for (int c = 0; c < 512; c++) { float t = st[c]; s += wq[c] * t * t; }
    const float WG2 = 1.0f / (512.f * 9.f);
    g_demod[b * 512 + o] = rsqrtf(s * WG2 + 1e-8f);
}

__global__ void xscale_kernel(const float* __restrict__ x) {
    int idx = blockIdx.x * blockDim.x + threadIdx.x;
    int x4 = idx & 15;
    int y  = (idx >> 4) & 63;
    int kk = (idx >> 10) & 255;
    int b  = idx >> 18;
    float se = g_style[b * 512 + 2 * kk];
    float so = g_style[b * 512 + 2 * kk + 1];
    const float4* xp = reinterpret_cast<const float4*>(x);
    float4 xe = xp[(b * 512 + 2 * kk) * 1024 + y * 16 + x4];
    float4 xo = xp[(b * 512 + 2 * kk + 1) * 1024 + y * 16 + x4];
    __half2 h[4];
    h[0] = __floats2half2_rn(xe.x * se, xo.x * so);
    h[1] = __floats2half2_rn(xe.y * se, xo.y * so);
    h[2] = __floats2half2_rn(xe.z * se, xo.z * so);
    h[3] = __floats2half2_rn(xe.w * se, xo.w * so);
    reinterpret_cast<uint4*>(g_x2)[(b * 256 + kk) * 1024 + y * 16 + x4] =
        *reinterpret_cast<uint4*>(h);
}

__global__ void wh2_kernel(const float* __restrict__ weight) {
    int o  = threadIdx.x;
    int kk = blockIdx.x / 9;
    int t  = blockIdx.x % 9;
    const float WG = 0.014731391274719739f;  // 1/sqrt(512*9)
    float we = weight[(o * 512 + 2 * kk) * 9 + t] * WG;
    float wo = weight[(o * 512 + 2 * kk + 1) * 9 + t] * WG;
    g_wh2[(kk * 9 + t) * 512 + o] = __floats2half2_rn(we, wo);
}

// ---------------- conv: implicit GEMM, fp16 mma.sync, fp32 accum ----------------
__device__ __forceinline__ void mma16816(float& c0, float& c1, float& c2, float& c3,
                                         uint32_t a0, uint32_t a1, uint32_t a2, uint32_t a3,
                                         uint32_t b0, uint32_t b1) {
    asm volatile(
        "mma.sync.aligned.m16n8k16.row.col.f32.f16.f16.f32 "
        "{%0,%1,%2,%3}, {%4,%5,%6,%7}, {%8,%9}, {%0,%1,%2,%3};\n"
        : "+f"(c0), "+f"(c1), "+f"(c2), "+f"(c3)
        : "r"(a0), "r"(a1), "r"(a2), "r"(a3), "r"(b0), "r"(b1));
}

__device__ __forceinline__ void cp16(uint32_t dst, const void* src) {
    asm volatile("cp.async.cg.shared.global [%0], [%1], 16;\n" :: "r"(dst), "l"(src));
}
__device__ __forceinline__ void cp_commit() {
    asm volatile("cp.async.commit_group;\n" ::: "memory");
}

#define XS_K 440          // half2 stride per kk slab (6*72 rows + pad), conflict-free
#define XS_R 72           // half2 stride per input row
#define WS_T (16 * 72)    // half2 stride per tap
#define WS_K 72           // half2 stride per kk (64 used; 72 keeps b-loads conflict-free)
#define STAGE (16 * XS_K + 9 * WS_T)   // 17408 half2 = 69632 B per stage

// load one K-chunk (32 input channels) into a stage: X slab + weights, via cp.async
__device__ __forceinline__ void load_chunk(__half2* Xs, __half2* Ws,
                                           int b, int kk0, int y0, int n0, int tid) {
    uint32_t xbase = (uint32_t)__cvta_generic_to_shared(Xs);
    // X: 16 kk x 6 rows x 16 vec16B  (interior cols stored at half2 offset 4..67)
#pragma unroll
    for (int i = 0; i < 6; i++) {
        int idx = tid + i * 256;           // 0..1535
        int v   = idx & 15;
        int t   = idx >> 4;                // 0..95
        int kkL = t / 6;
        int rr  = t - kkL * 6;
        int yy  = y0 - 1 + rr;
        if (yy >= 0 && yy < 64) {
            uint32_t dst = xbase + (uint32_t)(kkL * XS_K + rr * XS_R + 4) * 4u + v * 16u;
            const __half2* src = g_x2 + ((size_t)((b * 256 + kk0 + kkL) * 64 + yy)) * 64 + v * 4;
            cp16(dst, src);
        }
    }
    uint32_t wbase = (uint32_t)__cvta_generic_to_shared(Ws);
    // W: 9 taps x (16 kk x 16 vec16B) ; exactly 256 vecs per tap
#pragma unroll
    for (int tp = 0; tp < 9; tp++) {
        int kkL = tid >> 4;
        int v   = tid & 15;
        uint32_t dst = wbase + (uint32_t)(tp * WS_T + kkL * WS_K) * 4u + v * 16u;
        const __half2* src = g_wh2 + ((size_t)(kk0 + kkL) * 9 + tp) * 512 + n0 + v * 4;
        cp16(dst, src);
    }
}

__global__ void __launch_bounds__(256, 1) conv_kernel(float* __restrict__ out) {
    extern __shared__ __align__(16) __half2 smem[];

    const int n0  = blockIdx.x * 64;
    const int y0  = blockIdx.y * 4;
    const int b   = blockIdx.z;
    const int tid = threadIdx.x;
    const int w = tid >> 5, lane = tid & 31;
    const int g = lane >> 2, t4 = lane & 3;
    const int r = w >> 1, xb = (w & 1) * 32;

    // zero both X slabs once (halo / pad columns stay zero for all chunks)
    {
        uint4 zz = make_uint4(0, 0, 0, 0);
#pragma unroll 1
        for (int st = 0; st < 2; st++) {
            uint4* p = reinterpret_cast<uint4*>(smem + st * STAGE);
            for (int i = tid; i < 16 * XS_K / 4; i += 256) p[i] = zz;
        }
    }
    __syncthreads();

    float acc[64];
#pragma unroll
    for (int i = 0; i < 64; i++) acc[i] = 0.f;

    // prologue: load chunk 0 into stage 0
    load_chunk(smem, smem + 16 * XS_K, b, 0, y0, n0, tid);
    cp_commit();

#pragma unroll 1
    for (int c = 0; c < 16; c++) {
        // issue next chunk's loads into the other stage
        if (c + 1 < 16) {
            __half2* base = smem + ((c + 1) & 1) * STAGE;
            load_chunk(base, base + 16 * XS_K, b, (c + 1) * 16, y0, n0, tid);
            cp_commit();
            asm volatile("cp.async.wait_group 1;\n" ::: "memory");
        } else {
            asm volatile("cp.async.wait_group 0;\n" ::: "memory");
        }
        __syncthreads();

        const __half2* Xs = smem + (c & 1) * STAGE;
        const __half2* Ws = Xs + 16 * XS_K;

#pragma unroll 1
        for (int tap = 0; tap < 9; tap++) {
            const int ky = tap / 3, kx = tap - ky * 3;
#pragma unroll
            for (int ks = 0; ks < 2; ks++) {
                const int kkA = 8 * ks + t4;
                uint32_t a[2][4];
#pragma unroll
                for (int s = 0; s < 2; s++) {
                    int col = 3 + xb + 16 * s + kx + g;   // interior base at half2 col 4, tap kx-1
                    const __half2* base = Xs + kkA * XS_K + (r + ky) * XS_R;
                    a[s][0] = *reinterpret_cast<const uint32_t*>(base + col);
                    a[s][1] = *reinterpret_cast<const uint32_t*>(base + col + 8);
                    a[s][2] = *reinterpret_cast<const uint32_t*>(base + 4 * XS_K + col);
                    a[s][3] = *reinterpret_cast<const uint32_t*>(base + 4 * XS_K + col + 8);
                }
#pragma unroll
                for (int nc = 0; nc < 8; nc++) {
                    const __half2* wb = Ws + tap * WS_T + kkA * WS_K + nc * 8 + g;
                    uint32_t b0 = *reinterpret_cast<const uint32_t*>(wb);
                    uint32_t b1 = *reinterpret_cast<const uint32_t*>(wb + 4 * WS_K);
#pragma unroll
                    for (int s = 0; s < 2; s++) {
                        float* cc = acc + (s * 8 + nc) * 4;
                        mma16816(cc[0], cc[1], cc[2], cc[3],
                                 a[s][0], a[s][1], a[s][2], a[s][3], b0, b1);
                    }
                }
            }
        }
        __syncthreads();   // protect stage (c&1) before it is refilled at iter c+1
    }

    // epilogue: multiply by demod, store fp32
    const int y = y0 + r;
#pragma unroll
    for (int nc = 0; nc < 8; nc++) {
        int o = n0 + nc * 8 + 2 * t4;
        float d0 = g_demod[b * 512 + o];
        float d1 = g_demod[b * 512 + o + 1];
        size_t base0 = (((size_t)b * 512 + o) * 64 + y) * 64;
#pragma unroll
        for (int s = 0; s < 2; s++) {
            int xx = xb + 16 * s + g;
            float* cc = acc + (s * 8 + nc) * 4;
            out[base0 + xx]            = cc[0] * d0;
            out[base0 + 4096 + xx]     = cc[1] * d1;
            out[base0 + xx + 8]        = cc[2] * d0;
            out[base0 + 4096 + xx + 8] = cc[3] * d1;
        }
    }
}

// ---------------- launch ----------------
extern "C" void kernel_launch(void* const* d_in, const int* in_sizes, int n_in,
                              void* d_out, int out_size) {
    const float* x      = (const float*)d_in[0];   // [16,512,64,64]
    const float* w      = (const float*)d_in[1];   // [16,512]
    const float* weight = (const float*)d_in[2];   // [512,512,3,3]
    const float* mw     = (const float*)d_in[3];   // [512,512]
    const float* mb     = (const float*)d_in[4];   // [512]
    float* out = (float*)d_out;

    style_kernel<<<16, 512>>>(w, mw, mb);
    wsq_kernel<<<512, 512>>>(weight);
    demod_kernel<<<32, 256>>>();
    xscale_kernel<<<16384, 256>>>(x);
    wh2_kernel<<<256 * 9, 512>>>(weight);

    size_t shmem = (size_t)(2 * STAGE) * sizeof(__half2);  // 139264 B
    cudaFuncSetAttribute(conv_kernel, cudaFuncAttributeMaxDynamicSharedMemorySize,
                         (int)shmem);
    dim3 grid(8, 16, 16);   // (out-ch/64, H/4, B)
    conv_kernel<<<grid, 256, shmem>>>(out);
}

// round 3
// speedup vs baseline: 1.3374x; 1.0018x over previous
#include <cuda_runtime.h>
#include <cuda_fp16.h>
#include <cstdint>

#define NB   16
#define CIN  512
#define COUT 512
#define HH   64
#define WWD  64
#define KKC  256   // channel pairs (half2)

// ---------------- device scratch (static, allowed) ----------------
static __device__ float   g_style[NB * CIN];
static __device__ float   g_wsq[COUT * CIN];
static __device__ float   g_demod[NB * COUT];
static __device__ __half2 g_x2[(size_t)NB * KKC * HH * WWD];   // [b][kk][y][x], 67MB
static __device__ __half2 g_wh2[KKC * 9 * COUT];               // [kk][tap][o], 4.7MB

// ---------------- prep kernels ----------------
__global__ void style_kernel(const float* __restrict__ w,
                             const float* __restrict__ mw,
                             const float* __restrict__ mb) {
    __shared__ float sw[512];
    int b = blockIdx.x, c = threadIdx.x;
    sw[c] = w[b * 512 + c];
    __syncthreads();
    float acc = 0.f;
    const float* row = mw + c * 512;
#pragma unroll 8
    for (int d = 0; d < 512; d++) acc += sw[d] * row[d];
    g_style[b * 512 + c] = acc * 0.04419417382415922f + mb[c];
}

__global__ void wsq_kernel(const float* __restrict__ weight) {
    int o = blockIdx.x, c = threadIdx.x;
    const float* p = weight + (o * 512 + c) * 9;
    float s = 0.f;
#pragma unroll
    for (int t = 0; t < 9; t++) { float v = p[t]; s += v * v; }
    g_wsq[o * 512 + c] = s;
}

__global__ void demod_kernel() {
    int gid = blockIdx.x * blockDim.x + threadIdx.x;  // 8192 threads
    int o = gid >> 4, b = gid & 15;
    const float* wq = g_wsq + o * 512;
    const float* st = g_style + b * 512;
    float s = 0.f;
#pragma unroll 8
    for (int c = 0; c < 512; c++) { float t = st[c]; s += wq[c] * t * t; }
    const float WG2 = 1.0f / (512.f * 9.f);
    g_demod[b * 512 + o] = rsqrtf(s * WG2 + 1e-8f);
}

__global__ void xscale_kernel(const float* __restrict__ x) {
    int idx = blockIdx.x * blockDim.x + threadIdx.x;
    int x4 = idx & 15;
    int y  = (idx >> 4) & 63;
    int kk = (idx >> 10) & 255;
    int b  = idx >> 18;
    float se = g_style[b * 512 + 2 * kk];
    float so = g_style[b * 512 + 2 * kk + 1];
    const float4* xp = reinterpret_cast<const float4*>(x);
    float4 xe = xp[(b * 512 + 2 * kk) * 1024 + y * 16 + x4];
    float4 xo = xp[(b * 512 + 2 * kk + 1) * 1024 + y * 16 + x4];
    __half2 h[4];
    h[0] = __floats2half2_rn(xe.x * se, xo.x * so);
    h[1] = __floats2half2_rn(xe.y * se, xo.y * so);
    h[2] = __floats2half2_rn(xe.z * se, xo.z * so);
    h[3] = __floats2half2_rn(xe.w * se, xo.w * so);
    reinterpret_cast<uint4*>(g_x2)[(b * 256 + kk) * 1024 + y * 16 + x4] =
        *reinterpret_cast<uint4*>(h);
}

__global__ void wh2_kernel(const float* __restrict__ weight) {
    int o  = threadIdx.x;
    int kk = blockIdx.x / 9;
    int t  = blockIdx.x % 9;
    const float WG = 0.014731391274719739f;  // 1/sqrt(512*9)
    float we = weight[(o * 512 + 2 * kk) * 9 + t] * WG;
    float wo = weight[(o * 512 + 2 * kk + 1) * 9 + t] * WG;
    g_wh2[(kk * 9 + t) * 512 + o] = __floats2half2_rn(we, wo);
}

// ---------------- conv: implicit GEMM, fp16 mma.sync, fp32 accum ----------------
__device__ __forceinline__ void mma16816(float& c0, float& c1, float& c2, float& c3,
                                         uint32_t a0, uint32_t a1, uint32_t a2, uint32_t a3,
                                         uint32_t b0, uint32_t b1) {
    asm volatile(
        "mma.sync.aligned.m16n8k16.row.col.f32.f16.f16.f32 "
        "{%0,%1,%2,%3}, {%4,%5,%6,%7}, {%8,%9}, {%0,%1,%2,%3};\n"
        : "+f"(c0), "+f"(c1), "+f"(c2), "+f"(c3)
        : "r"(a0), "r"(a1), "r"(a2), "r"(a3), "r"(b0), "r"(b1));
}

__device__ __forceinline__ void cp16(uint32_t dst, const void* src) {
    asm volatile("cp.async.cg.shared.global [%0], [%1], 16;\n" :: "r"(dst), "l"(src));
}
__device__ __forceinline__ void cp_commit() {
    asm volatile("cp.async.commit_group;\n" ::: "memory");
}

#define XS_K 440          // half2 stride per kk slab (6*72 rows + pad), conflict-free
#define XS_R 72           // half2 stride per input row
#define WS_T (16 * 72)    // half2 stride per tap
#define WS_K 72           // half2 stride per kk (64 used; 72 keeps b-loads conflict-free)
#define STAGE (16 * XS_K + 9 * WS_T)   // 17408 half2 = 69632 B per stage

// load one K-chunk (32 input channels) into a stage: X slab + weights, via cp.async
__device__ __forceinline__ void load_chunk(__half2* Xs, __half2* Ws,
                                           int b, int kk0, int y0, int n0, int tid) {
    uint32_t xbase = (uint32_t)__cvta_generic_to_shared(Xs);
    // X: 16 kk x 6 rows x 16 vec16B  (interior cols stored at half2 offset 4..67)
#pragma unroll
    for (int i = 0; i < 6; i++) {
        int idx = tid + i * 256;           // 0..1535
        int v   = idx & 15;
        int t   = idx >> 4;                // 0..95
        int kkL = t / 6;
        int rr  = t - kkL * 6;
        int yy  = y0 - 1 + rr;
        if (yy >= 0 && yy < 64) {
            uint32_t dst = xbase + (uint32_t)(kkL * XS_K + rr * XS_R + 4) * 4u + v * 16u;
            const __half2* src = g_x2 + ((size_t)((b * 256 + kk0 + kkL) * 64 + yy)) * 64 + v * 4;
            cp16(dst, src);
        }
    }
    uint32_t wbase = (uint32_t)__cvta_generic_to_shared(Ws);
    // W: 9 taps x (16 kk x 16 vec16B) ; exactly 256 vecs per tap
#pragma unroll
    for (int tp = 0; tp < 9; tp++) {
        int kkL = tid >> 4;
        int v   = tid & 15;
        uint32_t dst = wbase + (uint32_t)(tp * WS_T + kkL * WS_K) * 4u + v * 16u;
        const __half2* src = g_wh2 + ((size_t)(kk0 + kkL) * 9 + tp) * 512 + n0 + v * 4;
        cp16(dst, src);
    }
}

__global__ void __launch_bounds__(256, 1) conv_kernel(float* __restrict__ out) {
    extern __shared__ __align__(16) __half2 smem[];

    const int n0  = blockIdx.x * 64;
    const int y0  = blockIdx.y * 4;
    const int b   = blockIdx.z;
    const int tid = threadIdx.x;
    const int w = tid >> 5, lane = tid & 31;
    const int g = lane >> 2, t4 = lane & 3;
    const int r = w >> 1, xb = (w & 1) * 32;

    // zero both X slabs once (halo / pad columns stay zero for all chunks)
    {
        uint4 zz = make_uint4(0, 0, 0, 0);
#pragma unroll 1
        for (int st = 0; st < 2; st++) {
            uint4* p = reinterpret_cast<uint4*>(smem + st * STAGE);
            for (int i = tid; i < 16 * XS_K / 4; i += 256) p[i] = zz;
        }
    }
    __syncthreads();

    float acc[64];
#pragma unroll
    for (int i = 0; i < 64; i++) acc[i] = 0.f;

    // prologue: load chunk 0 into stage 0
    load_chunk(smem, smem + 16 * XS_K, b, 0, y0, n0, tid);
    cp_commit();

#pragma unroll 1
    for (int c = 0; c < 16; c++) {
        // issue next chunk's loads into the other stage
        if (c + 1 < 16) {
            __half2* base = smem + ((c + 1) & 1) * STAGE;
            load_chunk(base, base + 16 * XS_K, b, (c + 1) * 16, y0, n0, tid);
            cp_commit();
            asm volatile("cp.async.wait_group 1;\n" ::: "memory");
        } else {
            asm volatile("cp.async.wait_group 0;\n" ::: "memory");
        }
        __syncthreads();

        const __half2* Xs = smem + (c & 1) * STAGE;
        const __half2* Ws = Xs + 16 * XS_K;

#pragma unroll 1
        for (int tap = 0; tap < 9; tap++) {
            const int ky = tap / 3, kx = tap - ky * 3;
#pragma unroll
            for (int ks = 0; ks < 2; ks++) {
                const int kkA = 8 * ks + t4;
                uint32_t a[2][4];
#pragma unroll
                for (int s = 0; s < 2; s++) {
                    int col = 3 + xb + 16 * s + kx + g;   // interior base at half2 col 4, tap kx-1
                    const __half2* base = Xs + kkA * XS_K + (r + ky) * XS_R;
                    a[s][0] = *reinterpret_cast<const uint32_t*>(base + col);
                    a[s][1] = *reinterpret_cast<const uint32_t*>(base + col + 8);
                    a[s][2] = *reinterpret_cast<const uint32_t*>(base + 4 * XS_K + col);
                    a[s][3] = *reinterpret_cast<const uint32_t*>(base + 4 * XS_K + col + 8);
                }
#pragma unroll
                for (int nc = 0; nc < 8; nc++) {
                    const __half2* wb = Ws + tap * WS_T + kkA * WS_K + nc * 8 + g;
                    uint32_t b0 = *reinterpret_cast<const uint32_t*>(wb);
                    uint32_t b1 = *reinterpret_cast<const uint32_t*>(wb + 4 * WS_K);
#pragma unroll
                    for (int s = 0; s < 2; s++) {
                        float* cc = acc + (s * 8 + nc) * 4;
                        mma16816(cc[0], cc[1], cc[2], cc[3],
                                 a[s][0], a[s][1], a[s][2], a[s][3], b0, b1);
                    }
                }
            }
        }
        __syncthreads();   // protect stage (c&1) before it is refilled at iter c+1
    }

    // epilogue: multiply by demod, store fp32
    const int y = y0 + r;
#pragma unroll
    for (int nc = 0; nc < 8; nc++) {
        int o = n0 + nc * 8 + 2 * t4;
        float d0 = g_demod[b * 512 + o];
        float d1 = g_demod[b * 512 + o + 1];
        size_t base0 = (((size_t)b * 512 + o) * 64 + y) * 64;
#pragma unroll
        for (int s = 0; s < 2; s++) {
            int xx = xb + 16 * s + g;
            float* cc = acc + (s * 8 + nc) * 4;
            out[base0 + xx]            = cc[0] * d0;
            out[base0 + 4096 + xx]     = cc[1] * d1;
            out[base0 + xx + 8]        = cc[2] * d0;
            out[base0 + 4096 + xx + 8] = cc[3] * d1;
        }
    }
}

// ---------------- launch ----------------
extern "C" void kernel_launch(void* const* d_in, const int* in_sizes, int n_in,
                              void* d_out, int out_size) {
    const float* x      = (const float*)d_in[0];   // [16,512,64,64]
    const float* w      = (const float*)d_in[1];   // [16,512]
    const float* weight = (const float*)d_in[2];   // [512,512,3,3]
    const float* mw     = (const float*)d_in[3];   // [512,512]
    const float* mb     = (const float*)d_in[4];   // [512]
    float* out = (float*)d_out;

    style_kernel<<<16, 512>>>(w, mw, mb);
    wsq_kernel<<<512, 512>>>(weight);
    demod_kernel<<<32, 256>>>();
    xscale_kernel<<<16384, 256>>>(x);
    wh2_kernel<<<256 * 9, 512>>>(weight);

    size_t shmem = (size_t)(2 * STAGE) * sizeof(__half2);  // 139264 B
    cudaFuncSetAttribute(conv_kernel, cudaFuncAttributeMaxDynamicSharedMemorySize,
                         (int)shmem);
    dim3 grid(8, 16, 16);   // (out-ch/64, H/4, B)
    conv_kernel<<<grid, 256, shmem>>>(out);
}